// round 12
// baseline (speedup 1.0000x reference)
#include <cuda_runtime.h>
#include <cuda_bf16.h>
#include <math.h>

// ---------------------------------------------------------------------------
// KroneckerMoE v12 (= v11 with the X-convert indexing bug fixed):
//   K0: preconvert X,W fp32->bf16 (128B-in/thread, MLP=8) + A,B frag split
//   K1: router logits (bf16 out), 4-stage cp.async, 1 sync/iter, dyn smem
//   K2a: routing: approx top-4 -> exact fp32 rerank -> softmax (scale folded)
//   K2b: expert compute: tensor-core bilinear (R9-proven config)
// ---------------------------------------------------------------------------

#define ROUTER_K   1024
#define MAX_TOKENS 16384
#define MAX_E      256

__device__ unsigned g_lb[(size_t)MAX_TOKENS * MAX_E / 2];        // logits bf16x2
__device__ unsigned g_xb[(size_t)MAX_TOKENS * (ROUTER_K / 2)];   // bf16x2
__device__ unsigned g_wb[(size_t)MAX_E * (ROUTER_K / 2)];        // bf16x2
__device__ uint4 g_Ah[MAX_E * 2 * 2 * 32];
__device__ uint4 g_Al[MAX_E * 2 * 2 * 32];
__device__ uint2 g_Bh[MAX_E * 2 * 4 * 32];
__device__ uint2 g_Bl[MAX_E * 2 * 4 * 32];
__device__ int2   g_eidx[MAX_TOKENS];
__device__ float2 g_gate[MAX_TOKENS];

// ======================= helpers =========================
__device__ __forceinline__ void mma_bf16(float d[4], const unsigned a[4], const unsigned b[2]) {
    asm volatile(
        "mma.sync.aligned.m16n8k16.row.col.f32.bf16.bf16.f32 "
        "{%0,%1,%2,%3}, {%4,%5,%6,%7}, {%8,%9}, {%0,%1,%2,%3};\n"
        : "+f"(d[0]), "+f"(d[1]), "+f"(d[2]), "+f"(d[3])
        : "r"(a[0]), "r"(a[1]), "r"(a[2]), "r"(a[3]), "r"(b[0]), "r"(b[1]));
}
__device__ __forceinline__ unsigned cvt2_bf16(float hi, float lo) {
    unsigned d;
    asm("cvt.rn.bf16x2.f32 %0, %1, %2;" : "=r"(d) : "f"(hi), "f"(lo));
    return d;
}
__device__ __forceinline__ float bf16lo_f(unsigned u) { return __uint_as_float(u << 16); }
__device__ __forceinline__ float bf16hi_f(unsigned u) { return __uint_as_float(u & 0xffff0000u); }
__device__ __forceinline__ void split_pair(float e0, float e1, unsigned& h, unsigned& l) {
    h = cvt2_bf16(e1, e0);
    float r0 = e0 - bf16lo_f(h);
    float r1 = e1 - bf16hi_f(h);
    l = cvt2_bf16(r1, r0);
}
__device__ __forceinline__ bool pair_better(float v, int i, float w, int j) {
    return (v > w) || (v == w && i < j);
}
__device__ __forceinline__ void cp_async16(void* smem, const void* gmem) {
    unsigned s = (unsigned)__cvta_generic_to_shared(smem);
    asm volatile("cp.async.cg.shared.global [%0], [%1], 16;" :: "r"(s), "l"(gmem));
}

// ========= Kernel 0: X,W bf16 convert (128B in / 64B out per thread) =======
__global__ __launch_bounds__(256)
void convert_kernel(const float* __restrict__ X, const float* __restrict__ W,
                    const float* __restrict__ Ae, const float* __restrict__ Be,
                    int nx32, int nw32, int E) {
    int i = blockIdx.x * blockDim.x + threadIdx.x;
    if (i < nx32) {
        const float4* src = (const float4*)X + (size_t)i * 8;
        uint4* dst = (uint4*)g_xb + (size_t)i * 4;
        float4 v[8];
        #pragma unroll
        for (int q = 0; q < 8; q++) v[q] = src[q];
        #pragma unroll
        for (int h = 0; h < 4; h++) {
            dst[h] = make_uint4(
                cvt2_bf16(v[2*h].y,   v[2*h].x),   cvt2_bf16(v[2*h].w,   v[2*h].z),
                cvt2_bf16(v[2*h+1].y, v[2*h+1].x), cvt2_bf16(v[2*h+1].w, v[2*h+1].z));
        }
    } else if (i < nx32 + nw32) {
        int j = i - nx32;
        const float4* src = (const float4*)W + (size_t)j * 8;
        uint4* dst = (uint4*)g_wb + (size_t)j * 4;
        float4 v[8];
        #pragma unroll
        for (int q = 0; q < 8; q++) v[q] = src[q];
        #pragma unroll
        for (int h = 0; h < 4; h++) {
            dst[h] = make_uint4(
                cvt2_bf16(v[2*h].y,   v[2*h].x),   cvt2_bf16(v[2*h].w,   v[2*h].z),
                cvt2_bf16(v[2*h+1].y, v[2*h+1].x), cvt2_bf16(v[2*h+1].w, v[2*h+1].z));
        }
    } else {
        int j = i - nx32 - nw32;
        int e = j >> 5;
        if (e >= E) return;
        int lane = j & 31;
        int g = lane >> 2, t = lane & 3;
        #pragma unroll
        for (int kt = 0; kt < 2; kt++)
            #pragma unroll
            for (int mt = 0; mt < 2; mt++) {
                const float* ap = Ae + (size_t)e * 1024 + (mt * 16 + g) * 32 + kt * 16;
                float2 p0 = *(const float2*)(ap + 2 * t);
                float2 p1 = *(const float2*)(ap + 2 * t + 8);
                float2 p2 = *(const float2*)(ap + 8 * 32 + 2 * t);
                float2 p3 = *(const float2*)(ap + 8 * 32 + 2 * t + 8);
                uint4 h, l;
                split_pair(p0.x, p0.y, h.x, l.x);
                split_pair(p2.x, p2.y, h.y, l.y);
                split_pair(p1.x, p1.y, h.z, l.z);
                split_pair(p3.x, p3.y, h.w, l.w);
                int off = (((e * 2 + kt) * 2) + mt) * 32 + lane;
                g_Ah[off] = h;
                g_Al[off] = l;
            }
        #pragma unroll
        for (int kt = 0; kt < 2; kt++)
            #pragma unroll
            for (int nt = 0; nt < 4; nt++) {
                const float* bp = Be + (size_t)e * 1024 + (nt * 8 + g) * 32 + kt * 16;
                float2 q0 = *(const float2*)(bp + 2 * t);
                float2 q1 = *(const float2*)(bp + 2 * t + 8);
                uint2 h, l;
                split_pair(q0.x, q0.y, h.x, l.x);
                split_pair(q1.x, q1.y, h.y, l.y);
                int off = (((e * 2 + kt) * 4) + nt) * 32 + lane;
                g_Bh[off] = h;
                g_Bl[off] = l;
            }
    }
}

// ===== Kernel 1: bf16 mma router, BN=128, 4-stage cp.async, bf16 out ======
#define R_BM 128
#define R_BN 128
#define R_BK 32
#define XPAD 20
#define R_NI (ROUTER_K / R_BK)   // 32
#define NSTAGE 4
#define STG_WORDS (R_BM * XPAD)
#define R_SMEM (NSTAGE * 2 * STG_WORDS * 4)

__global__ __launch_bounds__(256)
void router_mma_kernel(int M, int E) {
    extern __shared__ unsigned smem_dyn[];
    unsigned* Xs = smem_dyn;
    unsigned* Ws = smem_dyn + NSTAGE * STG_WORDS;
    const int bm   = blockIdx.x * R_BM;
    const int bn   = blockIdx.y * R_BN;
    const int tid  = threadIdx.x;
    const int wid  = tid >> 5;
    const int lane = tid & 31;
    const int wm   = wid & 3;
    const int wn   = wid >> 2;
    const int g    = lane >> 2;
    const int t    = lane & 3;

    float d[2][8][4];
    #pragma unroll
    for (int mt = 0; mt < 2; mt++)
        #pragma unroll
        for (int nt = 0; nt < 8; nt++)
            #pragma unroll
            for (int r = 0; r < 4; r++) d[mt][nt][r] = 0.f;

    const uint4* xb4 = (const uint4*)g_xb;
    const uint4* wb4 = (const uint4*)g_wb;

    const int r0 = tid >> 2;
    const int r1 = r0 + 64;
    const int q  = tid & 3;

    #pragma unroll
    for (int p = 0; p < NSTAGE - 1; p++) {
        const int kq = p * 4;
        unsigned* xsp = Xs + p * STG_WORDS;
        unsigned* wsp = Ws + p * STG_WORDS;
        cp_async16(&xsp[r0 * XPAD + q * 4], &xb4[(size_t)(bm + r0) * 128 + kq + q]);
        cp_async16(&xsp[r1 * XPAD + q * 4], &xb4[(size_t)(bm + r1) * 128 + kq + q]);
        cp_async16(&wsp[r0 * XPAD + q * 4], &wb4[(size_t)(bn + r0) * 128 + kq + q]);
        cp_async16(&wsp[r1 * XPAD + q * 4], &wb4[(size_t)(bn + r1) * 128 + kq + q]);
        asm volatile("cp.async.commit_group;");
    }

    for (int it = 0; it < R_NI; it++) {
        const int s = it & (NSTAGE - 1);
        const int rem = R_NI - 1 - it;
        if (rem >= 2)      asm volatile("cp.async.wait_group 2;");
        else if (rem == 1) asm volatile("cp.async.wait_group 1;");
        else               asm volatile("cp.async.wait_group 0;");
        __syncthreads();

        if (it + NSTAGE - 1 < R_NI) {
            const int s3 = (it + NSTAGE - 1) & (NSTAGE - 1);
            const int kq = (it + NSTAGE - 1) * 4;
            unsigned* xsp = Xs + s3 * STG_WORDS;
            unsigned* wsp = Ws + s3 * STG_WORDS;
            cp_async16(&xsp[r0 * XPAD + q * 4], &xb4[(size_t)(bm + r0) * 128 + kq + q]);
            cp_async16(&xsp[r1 * XPAD + q * 4], &xb4[(size_t)(bm + r1) * 128 + kq + q]);
            cp_async16(&wsp[r0 * XPAD + q * 4], &wb4[(size_t)(bn + r0) * 128 + kq + q]);
            cp_async16(&wsp[r1 * XPAD + q * 4], &wb4[(size_t)(bn + r1) * 128 + kq + q]);
            asm volatile("cp.async.commit_group;");
        }

        const unsigned* xss = Xs + s * STG_WORDS;
        const unsigned* wss = Ws + s * STG_WORDS;
        #pragma unroll
        for (int ks = 0; ks < 2; ks++) {
            const int kw = ks * 8 + t;
            unsigned a[2][4];
            #pragma unroll
            for (int mt = 0; mt < 2; mt++) {
                const int rb = wm * 32 + mt * 16;
                a[mt][0] = xss[(rb + g    ) * XPAD + kw];
                a[mt][1] = xss[(rb + g + 8) * XPAD + kw];
                a[mt][2] = xss[(rb + g    ) * XPAD + kw + 4];
                a[mt][3] = xss[(rb + g + 8) * XPAD + kw + 4];
            }
            unsigned b[8][2];
            #pragma unroll
            for (int nt = 0; nt < 8; nt++) {
                const int cb = wn * 64 + nt * 8;
                b[nt][0] = wss[(cb + g) * XPAD + kw];
                b[nt][1] = wss[(cb + g) * XPAD + kw + 4];
            }
            #pragma unroll
            for (int mt = 0; mt < 2; mt++)
                #pragma unroll
                for (int nt = 0; nt < 8; nt++)
                    mma_bf16(d[mt][nt], a[mt], b[nt]);
        }
    }

    const int E2 = E >> 1;
    #pragma unroll
    for (int mt = 0; mt < 2; mt++) {
        #pragma unroll
        for (int nt = 0; nt < 8; nt++) {
            const int row = bm + wm * 32 + mt * 16 + g;
            const int cw  = (bn + wn * 64 + nt * 8) / 2 + t;
            g_lb[(size_t)row * E2 + cw]       = cvt2_bf16(d[mt][nt][1], d[mt][nt][0]);
            g_lb[(size_t)(row + 8) * E2 + cw] = cvt2_bf16(d[mt][nt][3], d[mt][nt][2]);
        }
    }
}

// ============== Kernel 2a: routing (top-4 + exact rerank + softmax) ========
#define NCAND 4

__global__ __launch_bounds__(256)
void route_kernel(const float* __restrict__ x,
                  const float* __restrict__ RW,
                  const float* __restrict__ scale,
                  int M, int E) {
    const int wid  = threadIdx.x >> 5;
    const int lane = threadIdx.x & 31;
    const int n    = blockIdx.x * 8 + wid;
    if (n >= M) return;

    const int NJ = E >> 5;
    float lv[8];
    const __nv_bfloat16* lrow = (const __nv_bfloat16*)g_lb + (size_t)n * E;
    #pragma unroll
    for (int j = 0; j < 8; j++)
        lv[j] = (j < NJ) ? __bfloat162float(lrow[lane + 32 * j]) : -3.4e38f;

    float4 xr4[8];
    const float4* xg = (const float4*)(x + (size_t)n * 1024);
    #pragma unroll
    for (int q = 0; q < 8; q++) xr4[q] = xg[q * 32 + lane];

    int cand[NCAND];
    #pragma unroll
    for (int it = 0; it < NCAND; it++) {
        float bv = -3.4e38f; int be = 0x7fffffff;
        #pragma unroll
        for (int j = 0; j < 8; j++) {
            int e = lane + 32 * j;
            if (j < NJ && pair_better(lv[j], e, bv, be)) { bv = lv[j]; be = e; }
        }
        #pragma unroll
        for (int off = 16; off > 0; off >>= 1) {
            float ov = __shfl_xor_sync(0xffffffffu, bv, off);
            int   oe = __shfl_xor_sync(0xffffffffu, be, off);
            if (pair_better(ov, oe, bv, be)) { bv = ov; be = oe; }
        }
        cand[it] = be;
        if ((be & 31) == lane) lv[be >> 5] = -3.4e38f;
    }

    float s[NCAND];
    #pragma unroll
    for (int c = 0; c < NCAND; c++) {
        const float4* wr = (const float4*)(RW + (size_t)cand[c] * 1024);
        float acc = 0.f;
        #pragma unroll
        for (int q = 0; q < 8; q++) {
            float4 wv = wr[q * 32 + lane];
            acc += xr4[q].x * wv.x + xr4[q].y * wv.y + xr4[q].z * wv.z + xr4[q].w * wv.w;
        }
        s[c] = acc;
    }
    #pragma unroll
    for (int off = 16; off > 0; off >>= 1) {
        #pragma unroll
        for (int c = 0; c < NCAND; c++) s[c] += __shfl_xor_sync(0xffffffffu, s[c], off);
    }

    float v0 = s[0]; int c0 = 0;
    #pragma unroll
    for (int c = 1; c < NCAND; c++)
        if (pair_better(s[c], cand[c], v0, cand[c0])) { v0 = s[c]; c0 = c; }
    float v1 = -3.4e38f; int c1 = -1;
    #pragma unroll
    for (int c = 0; c < NCAND; c++)
        if (c != c0 && (c1 < 0 || pair_better(s[c], cand[c], v1, cand[c1]))) { v1 = s[c]; c1 = c; }

    if (lane == 0) {
        const float sc = *scale;
        const float tt = expf(v1 - v0);
        const float w0 = 1.f / (1.f + tt);
        g_eidx[n] = make_int2(cand[c0], cand[c1]);
        g_gate[n] = make_float2(w0 * sc, tt * w0 * sc);
    }
}

// ============== Kernel 2b: tensor-core expert compute (R9 config) ==========
#define TPB_TOK 4
#define XSTRIDE 36
#define YSTRIDE 34

__global__ __launch_bounds__(128, 4)
void expert_kernel(const float* __restrict__ x,
                   const float* __restrict__ bias,
                   float* __restrict__ out, int M) {
    __shared__ float XsAll[TPB_TOK][32 * XSTRIDE];
    const int wid  = threadIdx.x >> 5;
    const int lane = threadIdx.x & 31;
    const int n    = blockIdx.x * TPB_TOK + wid;
    if (n >= M) return;
    float* xs = XsAll[wid];
    const int g = lane >> 2;
    const int t = lane & 3;

    const int2   ee = g_eidx[n];
    const float2 ww = g_gate[n];
    const int e0 = ee.x, e1 = ee.y;
    const float w0 = ww.x, w1 = ww.y;

    {
        const float4* xg = (const float4*)(x + (size_t)n * 1024);
        #pragma unroll
        for (int i = 0; i < 8; i++) {
            int idx = i * 32 + lane;
            int r   = idx >> 3;
            int q   = idx & 7;
            float4 v = xg[idx];
            *(float4*)&xs[r * XSTRIDE + q * 4] = v;
        }
    }
    __syncwarp();

    unsigned xbh[2][4][2], xbl[2][4][2];
    #pragma unroll
    for (int kt = 0; kt < 2; kt++)
        #pragma unroll
        for (int nt = 0; nt < 4; nt++)
            #pragma unroll
            for (int part = 0; part < 2; part++) {
                int krow = kt * 16 + 2 * t + 8 * part;
                float e0f = xs[krow * XSTRIDE + nt * 8 + g];
                float e1f = xs[(krow + 1) * XSTRIDE + nt * 8 + g];
                split_pair(e0f, e1f, xbh[kt][nt][part], xbl[kt][nt][part]);
            }

    float Y[2][4][4];
    #pragma unroll
    for (int mt = 0; mt < 2; mt++)
        #pragma unroll
        for (int nt = 0; nt < 4; nt++)
            #pragma unroll
            for (int r = 0; r < 4; r++) Y[mt][nt][r] = 0.f;

    #pragma unroll
    for (int kk = 0; kk < 2; kk++) {
        const int   e = kk ? e1 : e0;
        const float w = kk ? w1 : w0;

        float tA[2][4][4];
        #pragma unroll
        for (int mt = 0; mt < 2; mt++)
            #pragma unroll
            for (int nt = 0; nt < 4; nt++)
                #pragma unroll
                for (int r = 0; r < 4; r++) tA[mt][nt][r] = 0.f;

        #pragma unroll
        for (int kt = 0; kt < 2; kt++) {
            #pragma unroll
            for (int mt = 0; mt < 2; mt++) {
                int off = (((e * 2 + kt) * 2) + mt) * 32 + lane;
                uint4 ah4 = g_Ah[off];
                uint4 al4 = g_Al[off];
                unsigned ah[4] = {ah4.x, ah4.y, ah4.z, ah4.w};
                unsigned al[4] = {al4.x, al4.y, al4.z, al4.w};
                #pragma unroll
                for (int nt = 0; nt < 4; nt++) {
                    mma_bf16(tA[mt][nt], ah, xbh[kt][nt]);
                    mma_bf16(tA[mt][nt], ah, xbl[kt][nt]);
                    mma_bf16(tA[mt][nt], al, xbh[kt][nt]);
                }
            }
        }

        unsigned th[2][2][4], tl[2][2][4];
        #pragma unroll
        for (int mt = 0; mt < 2; mt++)
            #pragma unroll
            for (int ktB = 0; ktB < 2; ktB++) {
                float c00 = w * tA[mt][2 * ktB][0],     c01 = w * tA[mt][2 * ktB][1];
                float c02 = w * tA[mt][2 * ktB][2],     c03 = w * tA[mt][2 * ktB][3];
                float c10 = w * tA[mt][2 * ktB + 1][0], c11 = w * tA[mt][2 * ktB + 1][1];
                float c12 = w * tA[mt][2 * ktB + 1][2], c13 = w * tA[mt][2 * ktB + 1][3];
                split_pair(c00, c01, th[mt][ktB][0], tl[mt][ktB][0]);
                split_pair(c02, c03, th[mt][ktB][1], tl[mt][ktB][1]);
                split_pair(c10, c11, th[mt][ktB][2], tl[mt][ktB][2]);
                split_pair(c12, c13, th[mt][ktB][3], tl[mt][ktB][3]);
            }

        #pragma unroll
        for (int kt = 0; kt < 2; kt++)
            #pragma unroll
            for (int nt = 0; nt < 4; nt++) {
                int off = (((e * 2 + kt) * 4) + nt) * 32 + lane;
                uint2 bh2 = g_Bh[off];
                uint2 bl2 = g_Bl[off];
                unsigned bh[2] = {bh2.x, bh2.y};
                unsigned bl[2] = {bl2.x, bl2.y};
                #pragma unroll
                for (int mt = 0; mt < 2; mt++) {
                    mma_bf16(Y[mt][nt], th[mt][kt], bh);
                    mma_bf16(Y[mt][nt], th[mt][kt], bl);
                    mma_bf16(Y[mt][nt], tl[mt][kt], bh);
                }
            }
    }

    __syncwarp();
    #pragma unroll
    for (int mt = 0; mt < 2; mt++)
        #pragma unroll
        for (int nt = 0; nt < 4; nt++) {
            int o0 = mt * 16 + g, p0 = nt * 8 + 2 * t;
            *(float2*)&xs[o0 * YSTRIDE + p0]       = make_float2(Y[mt][nt][0], Y[mt][nt][1]);
            *(float2*)&xs[(o0 + 8) * YSTRIDE + p0] = make_float2(Y[mt][nt][2], Y[mt][nt][3]);
        }
    __syncwarp();
    float* og = out + (size_t)n * 1024;
    #pragma unroll
    for (int i = 0; i < 32; i++) {
        int q = i * 32 + lane;
        og[q] = xs[i * YSTRIDE + lane] + bias[q];
    }
}

// ================================ launch ===================================
extern "C" void kernel_launch(void* const* d_in, const int* in_sizes, int n_in,
                              void* d_out, int out_size) {
    const float* x  = (const float*)d_in[0];
    const float* rw = (const float*)d_in[1];
    const float* Ae = (const float*)d_in[2];
    const float* Be = (const float*)d_in[3];
    const float* sc = (const float*)d_in[4];
    const float* bi = (const float*)d_in[5];
    float* out = (float*)d_out;

    const int M = in_sizes[0] / ROUTER_K;   // 16384
    const int E = in_sizes[1] / ROUTER_K;   // 256

    const int nx32 = (M * ROUTER_K) / 32;
    const int nw32 = (E * ROUTER_K) / 32;
    const int nfrag = E * 32;
    convert_kernel<<<(nx32 + nw32 + nfrag + 255) / 256, 256>>>(x, rw, Ae, Be, nx32, nw32, E);

    cudaFuncSetAttribute(router_mma_kernel,
                         cudaFuncAttributeMaxDynamicSharedMemorySize, R_SMEM);
    dim3 g1(M / R_BM, E / R_BN);
    router_mma_kernel<<<g1, 256, R_SMEM>>>(M, E);

    route_kernel<<<(M + 7) / 8, 256>>>(x, rw, sc, M, E);

    expert_kernel<<<(M + TPB_TOK - 1) / TPB_TOK, 128>>>(x, bi, out, M);
}

// round 13
// speedup vs baseline: 1.0902x; 1.0902x over previous
#include <cuda_runtime.h>
#include <cuda_bf16.h>
#include <math.h>

// ---------------------------------------------------------------------------
// KroneckerMoE v13:
//   K0: preconvert X,W fp32->bf16 (R9-proven 8-float form) + A,B frag split
//   K1: router logits (bf16 out), 4-stage cp.async, ldmatrix frag loads
//   K2a: routing: approx top-4 -> exact fp32 rerank -> softmax (scale folded)
//   K2b: expert compute: tensor-core bilinear (R9-proven config)
// ---------------------------------------------------------------------------

#define ROUTER_K   1024
#define MAX_TOKENS 16384
#define MAX_E      256

__device__ unsigned g_lb[(size_t)MAX_TOKENS * MAX_E / 2];        // logits bf16x2
__device__ unsigned g_xb[(size_t)MAX_TOKENS * (ROUTER_K / 2)];   // bf16x2
__device__ unsigned g_wb[(size_t)MAX_E * (ROUTER_K / 2)];        // bf16x2
__device__ uint4 g_Ah[MAX_E * 2 * 2 * 32];
__device__ uint4 g_Al[MAX_E * 2 * 2 * 32];
__device__ uint2 g_Bh[MAX_E * 2 * 4 * 32];
__device__ uint2 g_Bl[MAX_E * 2 * 4 * 32];
__device__ int2   g_eidx[MAX_TOKENS];
__device__ float2 g_gate[MAX_TOKENS];

// ======================= helpers =========================
__device__ __forceinline__ void mma_bf16(float d[4], const unsigned a[4], const unsigned b[2]) {
    asm volatile(
        "mma.sync.aligned.m16n8k16.row.col.f32.bf16.bf16.f32 "
        "{%0,%1,%2,%3}, {%4,%5,%6,%7}, {%8,%9}, {%0,%1,%2,%3};\n"
        : "+f"(d[0]), "+f"(d[1]), "+f"(d[2]), "+f"(d[3])
        : "r"(a[0]), "r"(a[1]), "r"(a[2]), "r"(a[3]), "r"(b[0]), "r"(b[1]));
}
__device__ __forceinline__ unsigned cvt2_bf16(float hi, float lo) {
    unsigned d;
    asm("cvt.rn.bf16x2.f32 %0, %1, %2;" : "=r"(d) : "f"(hi), "f"(lo));
    return d;
}
__device__ __forceinline__ float bf16lo_f(unsigned u) { return __uint_as_float(u << 16); }
__device__ __forceinline__ float bf16hi_f(unsigned u) { return __uint_as_float(u & 0xffff0000u); }
__device__ __forceinline__ void split_pair(float e0, float e1, unsigned& h, unsigned& l) {
    h = cvt2_bf16(e1, e0);
    float r0 = e0 - bf16lo_f(h);
    float r1 = e1 - bf16hi_f(h);
    l = cvt2_bf16(r1, r0);
}
__device__ __forceinline__ bool pair_better(float v, int i, float w, int j) {
    return (v > w) || (v == w && i < j);
}
__device__ __forceinline__ void cp_async16(void* smem, const void* gmem) {
    unsigned s = (unsigned)__cvta_generic_to_shared(smem);
    asm volatile("cp.async.cg.shared.global [%0], [%1], 16;" :: "r"(s), "l"(gmem));
}
__device__ __forceinline__ unsigned smem_u32(const void* p) {
    return (unsigned)__cvta_generic_to_shared(p);
}
__device__ __forceinline__ void ldsm_x4(unsigned& r0, unsigned& r1, unsigned& r2, unsigned& r3,
                                        unsigned addr) {
    asm volatile("ldmatrix.sync.aligned.m8n8.x4.shared.b16 {%0,%1,%2,%3}, [%4];"
                 : "=r"(r0), "=r"(r1), "=r"(r2), "=r"(r3) : "r"(addr));
}

// ========= Kernel 0: X,W bf16 convert + A,B frag split (R9 form) ========
__global__ __launch_bounds__(256)
void convert_kernel(const float* __restrict__ X, const float* __restrict__ W,
                    const float* __restrict__ Ae, const float* __restrict__ Be,
                    int nx8, int nw8, int E) {
    int i = blockIdx.x * blockDim.x + threadIdx.x;
    if (i < nx8) {
        float4 v0 = ((const float4*)X)[2 * (size_t)i];
        float4 v1 = ((const float4*)X)[2 * (size_t)i + 1];
        uint4 u = make_uint4(cvt2_bf16(v0.y, v0.x), cvt2_bf16(v0.w, v0.z),
                             cvt2_bf16(v1.y, v1.x), cvt2_bf16(v1.w, v1.z));
        ((uint4*)g_xb)[i] = u;
    } else if (i < nx8 + nw8) {
        int j = i - nx8;
        float4 v0 = ((const float4*)W)[2 * (size_t)j];
        float4 v1 = ((const float4*)W)[2 * (size_t)j + 1];
        uint4 u = make_uint4(cvt2_bf16(v0.y, v0.x), cvt2_bf16(v0.w, v0.z),
                             cvt2_bf16(v1.y, v1.x), cvt2_bf16(v1.w, v1.z));
        ((uint4*)g_wb)[j] = u;
    } else {
        int j = i - nx8 - nw8;
        int e = j >> 5;
        if (e >= E) return;
        int lane = j & 31;
        int g = lane >> 2, t = lane & 3;
        #pragma unroll
        for (int kt = 0; kt < 2; kt++)
            #pragma unroll
            for (int mt = 0; mt < 2; mt++) {
                const float* ap = Ae + (size_t)e * 1024 + (mt * 16 + g) * 32 + kt * 16;
                float2 p0 = *(const float2*)(ap + 2 * t);
                float2 p1 = *(const float2*)(ap + 2 * t + 8);
                float2 p2 = *(const float2*)(ap + 8 * 32 + 2 * t);
                float2 p3 = *(const float2*)(ap + 8 * 32 + 2 * t + 8);
                uint4 h, l;
                split_pair(p0.x, p0.y, h.x, l.x);
                split_pair(p2.x, p2.y, h.y, l.y);
                split_pair(p1.x, p1.y, h.z, l.z);
                split_pair(p3.x, p3.y, h.w, l.w);
                int off = (((e * 2 + kt) * 2) + mt) * 32 + lane;
                g_Ah[off] = h;
                g_Al[off] = l;
            }
        #pragma unroll
        for (int kt = 0; kt < 2; kt++)
            #pragma unroll
            for (int nt = 0; nt < 4; nt++) {
                const float* bp = Be + (size_t)e * 1024 + (nt * 8 + g) * 32 + kt * 16;
                float2 q0 = *(const float2*)(bp + 2 * t);
                float2 q1 = *(const float2*)(bp + 2 * t + 8);
                uint2 h, l;
                split_pair(q0.x, q0.y, h.x, l.x);
                split_pair(q1.x, q1.y, h.y, l.y);
                int off = (((e * 2 + kt) * 4) + nt) * 32 + lane;
                g_Bh[off] = h;
                g_Bl[off] = l;
            }
    }
}

// ===== Kernel 1: bf16 mma router, 4-stage cp.async, ldmatrix frags ======
#define R_BM 128
#define R_BN 128
#define R_BK 32
#define XPAD 20
#define R_NI (ROUTER_K / R_BK)   // 32
#define NSTAGE 4
#define STG_WORDS (R_BM * XPAD)
#define R_SMEM (NSTAGE * 2 * STG_WORDS * 4)

__global__ __launch_bounds__(256)
void router_mma_kernel(int M, int E) {
    extern __shared__ unsigned smem_dyn[];
    unsigned* Xs = smem_dyn;
    unsigned* Ws = smem_dyn + NSTAGE * STG_WORDS;
    const int bm   = blockIdx.x * R_BM;
    const int bn   = blockIdx.y * R_BN;
    const int tid  = threadIdx.x;
    const int wid  = tid >> 5;
    const int lane = tid & 31;
    const int wm   = wid & 3;
    const int wn   = wid >> 2;
    const int g    = lane >> 2;
    const int t    = lane & 3;
    const int lm   = lane >> 3;   // ldmatrix matrix index 0..3
    const int lr   = lane & 7;    // row within matrix

    float d[2][8][4];
    #pragma unroll
    for (int mt = 0; mt < 2; mt++)
        #pragma unroll
        for (int nt = 0; nt < 8; nt++)
            #pragma unroll
            for (int r = 0; r < 4; r++) d[mt][nt][r] = 0.f;

    const uint4* xb4 = (const uint4*)g_xb;
    const uint4* wb4 = (const uint4*)g_wb;

    const int r0 = tid >> 2;
    const int r1 = r0 + 64;
    const int q  = tid & 3;

    // ldmatrix per-lane word offsets within a stage (ks-dependent part added in loop)
    // A matrices: [rows+0 klo][rows+8 klo][rows+0 khi][rows+8 khi]
    const int a_row_off = ((lm & 1) << 3) + lr;        // +0/+8 row, lr
    const int a_wrd_off = (lm >> 1) << 2;              // +0/+4 words
    // B matrices: [nt klo][nt khi][nt+1 klo][nt+1 khi]
    const int b_col_off = ((lm >> 1) << 3) + lr;       // +0/+8 col (nt step), lr
    const int b_wrd_off = (lm & 1) << 2;               // +0/+4 words

    #pragma unroll
    for (int p = 0; p < NSTAGE - 1; p++) {
        const int kq = p * 4;
        unsigned* xsp = Xs + p * STG_WORDS;
        unsigned* wsp = Ws + p * STG_WORDS;
        cp_async16(&xsp[r0 * XPAD + q * 4], &xb4[(size_t)(bm + r0) * 128 + kq + q]);
        cp_async16(&xsp[r1 * XPAD + q * 4], &xb4[(size_t)(bm + r1) * 128 + kq + q]);
        cp_async16(&wsp[r0 * XPAD + q * 4], &wb4[(size_t)(bn + r0) * 128 + kq + q]);
        cp_async16(&wsp[r1 * XPAD + q * 4], &wb4[(size_t)(bn + r1) * 128 + kq + q]);
        asm volatile("cp.async.commit_group;");
    }

    for (int it = 0; it < R_NI; it++) {
        const int s = it & (NSTAGE - 1);
        const int rem = R_NI - 1 - it;
        if (rem >= 2)      asm volatile("cp.async.wait_group 2;");
        else if (rem == 1) asm volatile("cp.async.wait_group 1;");
        else               asm volatile("cp.async.wait_group 0;");
        __syncthreads();

        if (it + NSTAGE - 1 < R_NI) {
            const int s3 = (it + NSTAGE - 1) & (NSTAGE - 1);
            const int kq = (it + NSTAGE - 1) * 4;
            unsigned* xsp = Xs + s3 * STG_WORDS;
            unsigned* wsp = Ws + s3 * STG_WORDS;
            cp_async16(&xsp[r0 * XPAD + q * 4], &xb4[(size_t)(bm + r0) * 128 + kq + q]);
            cp_async16(&xsp[r1 * XPAD + q * 4], &xb4[(size_t)(bm + r1) * 128 + kq + q]);
            cp_async16(&wsp[r0 * XPAD + q * 4], &wb4[(size_t)(bn + r0) * 128 + kq + q]);
            cp_async16(&wsp[r1 * XPAD + q * 4], &wb4[(size_t)(bn + r1) * 128 + kq + q]);
            asm volatile("cp.async.commit_group;");
        }

        const unsigned* xss = Xs + s * STG_WORDS;
        const unsigned* wss = Ws + s * STG_WORDS;
        #pragma unroll
        for (int ks = 0; ks < 2; ks++) {
            unsigned a[2][4];
            #pragma unroll
            for (int mt = 0; mt < 2; mt++) {
                const int row = wm * 32 + mt * 16 + a_row_off;
                const int wrd = ks * 8 + a_wrd_off;
                ldsm_x4(a[mt][0], a[mt][1], a[mt][2], a[mt][3],
                        smem_u32(&xss[row * XPAD + wrd]));
            }
            unsigned b[8][2];
            #pragma unroll
            for (int pp = 0; pp < 4; pp++) {
                const int col = wn * 64 + pp * 16 + b_col_off;
                const int wrd = ks * 8 + b_wrd_off;
                ldsm_x4(b[2 * pp][0], b[2 * pp][1], b[2 * pp + 1][0], b[2 * pp + 1][1],
                        smem_u32(&wss[col * XPAD + wrd]));
            }
            #pragma unroll
            for (int mt = 0; mt < 2; mt++)
                #pragma unroll
                for (int nt = 0; nt < 8; nt++)
                    mma_bf16(d[mt][nt], a[mt], b[nt]);
        }
    }

    const int E2 = E >> 1;
    #pragma unroll
    for (int mt = 0; mt < 2; mt++) {
        #pragma unroll
        for (int nt = 0; nt < 8; nt++) {
            const int row = bm + wm * 32 + mt * 16 + g;
            const int cw  = (bn + wn * 64 + nt * 8) / 2 + t;
            g_lb[(size_t)row * E2 + cw]       = cvt2_bf16(d[mt][nt][1], d[mt][nt][0]);
            g_lb[(size_t)(row + 8) * E2 + cw] = cvt2_bf16(d[mt][nt][3], d[mt][nt][2]);
        }
    }
}

// ============== Kernel 2a: routing (top-4 + exact rerank + softmax) ========
#define NCAND 4

__global__ __launch_bounds__(256)
void route_kernel(const float* __restrict__ x,
                  const float* __restrict__ RW,
                  const float* __restrict__ scale,
                  int M, int E) {
    const int wid  = threadIdx.x >> 5;
    const int lane = threadIdx.x & 31;
    const int n    = blockIdx.x * 8 + wid;
    if (n >= M) return;

    const int NJ = E >> 5;
    float lv[8];
    const __nv_bfloat16* lrow = (const __nv_bfloat16*)g_lb + (size_t)n * E;
    #pragma unroll
    for (int j = 0; j < 8; j++)
        lv[j] = (j < NJ) ? __bfloat162float(lrow[lane + 32 * j]) : -3.4e38f;

    float4 xr4[8];
    const float4* xg = (const float4*)(x + (size_t)n * 1024);
    #pragma unroll
    for (int q = 0; q < 8; q++) xr4[q] = xg[q * 32 + lane];

    int cand[NCAND];
    #pragma unroll
    for (int it = 0; it < NCAND; it++) {
        float bv = -3.4e38f; int be = 0x7fffffff;
        #pragma unroll
        for (int j = 0; j < 8; j++) {
            int e = lane + 32 * j;
            if (j < NJ && pair_better(lv[j], e, bv, be)) { bv = lv[j]; be = e; }
        }
        #pragma unroll
        for (int off = 16; off > 0; off >>= 1) {
            float ov = __shfl_xor_sync(0xffffffffu, bv, off);
            int   oe = __shfl_xor_sync(0xffffffffu, be, off);
            if (pair_better(ov, oe, bv, be)) { bv = ov; be = oe; }
        }
        cand[it] = be;
        if ((be & 31) == lane) lv[be >> 5] = -3.4e38f;
    }

    float s[NCAND];
    #pragma unroll
    for (int c = 0; c < NCAND; c++) {
        const float4* wr = (const float4*)(RW + (size_t)cand[c] * 1024);
        float acc = 0.f;
        #pragma unroll
        for (int q = 0; q < 8; q++) {
            float4 wv = wr[q * 32 + lane];
            acc += xr4[q].x * wv.x + xr4[q].y * wv.y + xr4[q].z * wv.z + xr4[q].w * wv.w;
        }
        s[c] = acc;
    }
    #pragma unroll
    for (int off = 16; off > 0; off >>= 1) {
        #pragma unroll
        for (int c = 0; c < NCAND; c++) s[c] += __shfl_xor_sync(0xffffffffu, s[c], off);
    }

    float v0 = s[0]; int c0 = 0;
    #pragma unroll
    for (int c = 1; c < NCAND; c++)
        if (pair_better(s[c], cand[c], v0, cand[c0])) { v0 = s[c]; c0 = c; }
    float v1 = -3.4e38f; int c1 = -1;
    #pragma unroll
    for (int c = 0; c < NCAND; c++)
        if (c != c0 && (c1 < 0 || pair_better(s[c], cand[c], v1, cand[c1]))) { v1 = s[c]; c1 = c; }

    if (lane == 0) {
        const float sc = *scale;
        const float tt = expf(v1 - v0);
        const float w0 = 1.f / (1.f + tt);
        g_eidx[n] = make_int2(cand[c0], cand[c1]);
        g_gate[n] = make_float2(w0 * sc, tt * w0 * sc);
    }
}

// ============== Kernel 2b: tensor-core expert compute (R9 config) ==========
#define TPB_TOK 4
#define XSTRIDE 36
#define YSTRIDE 34

__global__ __launch_bounds__(128, 4)
void expert_kernel(const float* __restrict__ x,
                   const float* __restrict__ bias,
                   float* __restrict__ out, int M) {
    __shared__ float XsAll[TPB_TOK][32 * XSTRIDE];
    const int wid  = threadIdx.x >> 5;
    const int lane = threadIdx.x & 31;
    const int n    = blockIdx.x * TPB_TOK + wid;
    if (n >= M) return;
    float* xs = XsAll[wid];
    const int g = lane >> 2;
    const int t = lane & 3;

    const int2   ee = g_eidx[n];
    const float2 ww = g_gate[n];
    const int e0 = ee.x, e1 = ee.y;
    const float w0 = ww.x, w1 = ww.y;

    {
        const float4* xg = (const float4*)(x + (size_t)n * 1024);
        #pragma unroll
        for (int i = 0; i < 8; i++) {
            int idx = i * 32 + lane;
            int r   = idx >> 3;
            int q   = idx & 7;
            float4 v = xg[idx];
            *(float4*)&xs[r * XSTRIDE + q * 4] = v;
        }
    }
    __syncwarp();

    unsigned xbh[2][4][2], xbl[2][4][2];
    #pragma unroll
    for (int kt = 0; kt < 2; kt++)
        #pragma unroll
        for (int nt = 0; nt < 4; nt++)
            #pragma unroll
            for (int part = 0; part < 2; part++) {
                int krow = kt * 16 + 2 * t + 8 * part;
                float e0f = xs[krow * XSTRIDE + nt * 8 + g];
                float e1f = xs[(krow + 1) * XSTRIDE + nt * 8 + g];
                split_pair(e0f, e1f, xbh[kt][nt][part], xbl[kt][nt][part]);
            }

    float Y[2][4][4];
    #pragma unroll
    for (int mt = 0; mt < 2; mt++)
        #pragma unroll
        for (int nt = 0; nt < 4; nt++)
            #pragma unroll
            for (int r = 0; r < 4; r++) Y[mt][nt][r] = 0.f;

    #pragma unroll
    for (int kk = 0; kk < 2; kk++) {
        const int   e = kk ? e1 : e0;
        const float w = kk ? w1 : w0;

        float tA[2][4][4];
        #pragma unroll
        for (int mt = 0; mt < 2; mt++)
            #pragma unroll
            for (int nt = 0; nt < 4; nt++)
                #pragma unroll
                for (int r = 0; r < 4; r++) tA[mt][nt][r] = 0.f;

        #pragma unroll
        for (int kt = 0; kt < 2; kt++) {
            #pragma unroll
            for (int mt = 0; mt < 2; mt++) {
                int off = (((e * 2 + kt) * 2) + mt) * 32 + lane;
                uint4 ah4 = g_Ah[off];
                uint4 al4 = g_Al[off];
                unsigned ah[4] = {ah4.x, ah4.y, ah4.z, ah4.w};
                unsigned al[4] = {al4.x, al4.y, al4.z, al4.w};
                #pragma unroll
                for (int nt = 0; nt < 4; nt++) {
                    mma_bf16(tA[mt][nt], ah, xbh[kt][nt]);
                    mma_bf16(tA[mt][nt], ah, xbl[kt][nt]);
                    mma_bf16(tA[mt][nt], al, xbh[kt][nt]);
                }
            }
        }

        unsigned th[2][2][4], tl[2][2][4];
        #pragma unroll
        for (int mt = 0; mt < 2; mt++)
            #pragma unroll
            for (int ktB = 0; ktB < 2; ktB++) {
                float c00 = w * tA[mt][2 * ktB][0],     c01 = w * tA[mt][2 * ktB][1];
                float c02 = w * tA[mt][2 * ktB][2],     c03 = w * tA[mt][2 * ktB][3];
                float c10 = w * tA[mt][2 * ktB + 1][0], c11 = w * tA[mt][2 * ktB + 1][1];
                float c12 = w * tA[mt][2 * ktB + 1][2], c13 = w * tA[mt][2 * ktB + 1][3];
                split_pair(c00, c01, th[mt][ktB][0], tl[mt][ktB][0]);
                split_pair(c02, c03, th[mt][ktB][1], tl[mt][ktB][1]);
                split_pair(c10, c11, th[mt][ktB][2], tl[mt][ktB][2]);
                split_pair(c12, c13, th[mt][ktB][3], tl[mt][ktB][3]);
            }

        #pragma unroll
        for (int kt = 0; kt < 2; kt++)
            #pragma unroll
            for (int nt = 0; nt < 4; nt++) {
                int off = (((e * 2 + kt) * 4) + nt) * 32 + lane;
                uint2 bh2 = g_Bh[off];
                uint2 bl2 = g_Bl[off];
                unsigned bh[2] = {bh2.x, bh2.y};
                unsigned bl[2] = {bl2.x, bl2.y};
                #pragma unroll
                for (int mt = 0; mt < 2; mt++) {
                    mma_bf16(Y[mt][nt], th[mt][kt], bh);
                    mma_bf16(Y[mt][nt], th[mt][kt], bl);
                    mma_bf16(Y[mt][nt], tl[mt][kt], bh);
                }
            }
    }

    __syncwarp();
    #pragma unroll
    for (int mt = 0; mt < 2; mt++)
        #pragma unroll
        for (int nt = 0; nt < 4; nt++) {
            int o0 = mt * 16 + g, p0 = nt * 8 + 2 * t;
            *(float2*)&xs[o0 * YSTRIDE + p0]       = make_float2(Y[mt][nt][0], Y[mt][nt][1]);
            *(float2*)&xs[(o0 + 8) * YSTRIDE + p0] = make_float2(Y[mt][nt][2], Y[mt][nt][3]);
        }
    __syncwarp();
    float* og = out + (size_t)n * 1024;
    #pragma unroll
    for (int i = 0; i < 32; i++) {
        int q = i * 32 + lane;
        og[q] = xs[i * YSTRIDE + lane] + bias[q];
    }
}

// ================================ launch ===================================
extern "C" void kernel_launch(void* const* d_in, const int* in_sizes, int n_in,
                              void* d_out, int out_size) {
    const float* x  = (const float*)d_in[0];
    const float* rw = (const float*)d_in[1];
    const float* Ae = (const float*)d_in[2];
    const float* Be = (const float*)d_in[3];
    const float* sc = (const float*)d_in[4];
    const float* bi = (const float*)d_in[5];
    float* out = (float*)d_out;

    const int M = in_sizes[0] / ROUTER_K;   // 16384
    const int E = in_sizes[1] / ROUTER_K;   // 256

    const int nx8 = (M * ROUTER_K) / 8;
    const int nw8 = (E * ROUTER_K) / 8;
    const int nfrag = E * 32;
    convert_kernel<<<(nx8 + nw8 + nfrag + 255) / 256, 256>>>(x, rw, Ae, Be, nx8, nw8, E);

    cudaFuncSetAttribute(router_mma_kernel,
                         cudaFuncAttributeMaxDynamicSharedMemorySize, R_SMEM);
    dim3 g1(M / R_BM, E / R_BN);
    router_mma_kernel<<<g1, 256, R_SMEM>>>(M, E);

    route_kernel<<<(M + 7) / 8, 256>>>(x, rw, sc, M, E);

    expert_kernel<<<(M + TPB_TOK - 1) / TPB_TOK, 128>>>(x, bi, out, M);
}